// round 12
// baseline (speedup 1.0000x reference)
#include <cuda_runtime.h>
#include <cuda_fp16.h>
#include <stdint.h>

// Problem constants
#define BB 32
#define TT 2000
#define HH 768
#define SS 100
#define NVV 100
#define BSROWS 3200            // B*S
#define ROWSTRIDE 2100         // NV + T
#define K2 1536                // 2*H

// Block-range layout of mega_kernel (agg blocks handle FOUR segments each)
#define NBLK_AGG  (BSROWS / 4)           // 800
#define NBLK_VIS  (BB * 4)               // 128
#define NBLK_WC   384                    // 384 * 384 f4 = H*H/4
#define NBLK_MEGA (NBLK_AGG + NBLK_VIS + NBLK_WC)   // 1312 (single wave)

// ---------------------------------------------------------------------------
// Scratch (device globals; allocation forbidden)
// ---------------------------------------------------------------------------
__device__ unsigned short g_af[BSROWS * HH];    // fp16 segment means (A)
__device__ unsigned short g_w1h[HH * HH];       // fp16 hi of W1 (w[:, :768])
__device__ unsigned short g_w1l[HH * HH];       // fp16 lo of W1
__device__ float g_vispart[BB * 4 * HH];        // partial sums of vision rows
__device__ float g_v2[BB * HH];                 // vision @ W2^T + bias

// ---------------------------------------------------------------------------
// Helpers
// ---------------------------------------------------------------------------
__device__ __forceinline__ uint32_t smem_u32(const void* p) {
    uint32_t a;
    asm("{ .reg .u64 t; cvta.to.shared.u64 t, %1; cvt.u32.u64 %0, t; }" : "=r"(a) : "l"(p));
    return a;
}
__device__ __forceinline__ void cpasync16(uint32_t saddr, const void* g) {
    asm volatile("cp.async.cg.shared.global [%0], [%1], 16;" :: "r"(saddr), "l"(g));
}
#define CP_COMMIT() asm volatile("cp.async.commit_group;" ::: "memory")

__device__ __forceinline__ void ldsm_x4(uint32_t* r, uint32_t addr) {
    asm volatile("ldmatrix.sync.aligned.m8n8.x4.shared.b16 {%0,%1,%2,%3}, [%4];"
                 : "=r"(r[0]), "=r"(r[1]), "=r"(r[2]), "=r"(r[3]) : "r"(addr));
}
__device__ __forceinline__ void ldsm_x2(uint32_t* r, uint32_t addr) {
    asm volatile("ldmatrix.sync.aligned.m8n8.x2.shared.b16 {%0,%1}, [%2];"
                 : "=r"(r[0]), "=r"(r[1]) : "r"(addr));
}
__device__ __forceinline__ void mma_f16(float* c, const uint32_t* a, const uint32_t* b) {
    asm volatile("mma.sync.aligned.m16n8k16.row.col.f32.f16.f16.f32 "
                 "{%0,%1,%2,%3}, {%4,%5,%6,%7}, {%8,%9}, {%0,%1,%2,%3};"
                 : "+f"(c[0]), "+f"(c[1]), "+f"(c[2]), "+f"(c[3])
                 : "r"(a[0]), "r"(a[1]), "r"(a[2]), "r"(a[3]), "r"(b[0]), "r"(b[1]));
}

// fp16 hi/lo split (for W1)
__device__ __forceinline__ void splitw(float x, unsigned short& h, unsigned short& l) {
    __half hh = __float2half_rn(x);
    h = __half_as_ushort(hh);
    l = __half_as_ushort(__float2half_rn(x - __half2float(hh)));
}
// pack 4 floats -> 4 fp16 in a uint2
__device__ __forceinline__ uint2 pack4h(float4 v) {
    __half2 p01 = __floats2half2_rn(v.x, v.y);
    __half2 p23 = __floats2half2_rn(v.z, v.w);
    uint2 u;
    u.x = *reinterpret_cast<uint32_t*>(&p01);
    u.y = *reinterpret_cast<uint32_t*>(&p23);
    return u;
}

// accumulate a segment's rows (list in smem) into a float4 and store fp16 mean
__device__ __forceinline__ void seg_accum_store(const float* __restrict__ base,
                                                const unsigned short* __restrict__ list,
                                                int cnt, int h4, size_t orow) {
    float inv = (cnt > 0) ? (1.0f / (float)cnt) : 0.0f;
    float4 acc = make_float4(0.f, 0.f, 0.f, 0.f);
    int i = 0;
    for (; i + 8 <= cnt; i += 8) {
        float4 v[8];
        #pragma unroll
        for (int j = 0; j < 8; j++)
            v[j] = *(const float4*)&base[(size_t)list[i + j] * HH + h4 * 4];
        #pragma unroll
        for (int j = 0; j < 8; j++) {
            acc.x += v[j].x; acc.y += v[j].y; acc.z += v[j].z; acc.w += v[j].w;
        }
    }
    for (; i + 4 <= cnt; i += 4) {
        float4 v[4];
        #pragma unroll
        for (int j = 0; j < 4; j++)
            v[j] = *(const float4*)&base[(size_t)list[i + j] * HH + h4 * 4];
        #pragma unroll
        for (int j = 0; j < 4; j++) {
            acc.x += v[j].x; acc.y += v[j].y; acc.z += v[j].z; acc.w += v[j].w;
        }
    }
    for (; i < cnt; i++) {
        float4 v = *(const float4*)&base[(size_t)list[i] * HH + h4 * 4];
        acc.x += v.x; acc.y += v.y; acc.z += v.z; acc.w += v.w;
    }
    acc.x *= inv; acc.y *= inv; acc.z *= inv; acc.w *= inv;
    *(uint2*)&g_af[orow * HH + h4 * 4] = pack4h(acc);
}

// ---------------------------------------------------------------------------
// Mega kernel: block-range specialization fuses agg (4 segments per block) /
// vision partials / W1 split so they overlap on-chip. 192 threads per block.
// Grid 1312 blocks <= single-wave capacity: everything resident at once.
// ---------------------------------------------------------------------------
__global__ __launch_bounds__(192) void mega_kernel(const float* __restrict__ feat,
                                                   const int* __restrict__ mask,
                                                   const float* __restrict__ w) {
    const int blk = blockIdx.x;

    if (blk < NBLK_AGG) {
        // ---- segment means -> fp16. One block per (b, segment-quad). ----
        int b = blk / (SS / 4);
        int s0 = (blk % (SS / 4)) * 4;          // segments s0..s0+3

        __shared__ unsigned short lists[4][TT];  // 16 KB
        __shared__ int cnts[4];
        if (threadIdx.x < 4) cnts[threadIdx.x] = 0;
        __syncthreads();

        const int* mrow = mask + (size_t)b * TT;
        for (int t = threadIdx.x; t < TT; t += 192) {
            int m = mrow[t] - 1 - s0;           // 0..3 if in this quad
            if ((unsigned)m < 4u) {
                int pos = atomicAdd(&cnts[m], 1);
                lists[m][pos] = (unsigned short)t;
            }
        }
        __syncthreads();

        const float* base = feat + ((size_t)b * ROWSTRIDE + NVV) * HH;
        int h4 = threadIdx.x;                   // 0..191
        size_t row0 = (size_t)b * SS + s0;
        #pragma unroll
        for (int q = 0; q < 4; q++)
            seg_accum_store(base, lists[q], cnts[q], h4, row0 + q);

    } else if (blk < NBLK_AGG + NBLK_VIS) {
        // ---- vision partial sums: 25 rows per block ----
        int idx = blk - NBLK_AGG;
        int b = idx >> 2, part = idx & 3;
        const float* base = feat + ((size_t)b * ROWSTRIDE + part * 25) * HH;
        int h4 = threadIdx.x;
        float4 acc = make_float4(0.f, 0.f, 0.f, 0.f);
        int r = 0;
        for (; r + 4 <= 25; r += 4) {
            float4 v0 = *(const float4*)&base[(size_t)(r + 0) * HH + h4 * 4];
            float4 v1 = *(const float4*)&base[(size_t)(r + 1) * HH + h4 * 4];
            float4 v2 = *(const float4*)&base[(size_t)(r + 2) * HH + h4 * 4];
            float4 v3 = *(const float4*)&base[(size_t)(r + 3) * HH + h4 * 4];
            acc.x += v0.x + v1.x + v2.x + v3.x;
            acc.y += v0.y + v1.y + v2.y + v3.y;
            acc.z += v0.z + v1.z + v2.z + v3.z;
            acc.w += v0.w + v1.w + v2.w + v3.w;
        }
        for (; r < 25; r++) {
            float4 v = *(const float4*)&base[(size_t)r * HH + h4 * 4];
            acc.x += v.x; acc.y += v.y; acc.z += v.z; acc.w += v.w;
        }
        *(float4*)&g_vispart[(size_t)idx * HH + h4 * 4] = acc;

    } else {
        // ---- W1 split into fp16 hi/lo: 384 float4s per block ----
        int wblk = blk - (NBLK_AGG + NBLK_VIS);
        int i0 = wblk * 384 + threadIdx.x;
        #pragma unroll
        for (int j = 0; j < 2; j++) {
            int idx = i0 + j * 192;
            int n = idx / (HH / 4);
            int k4 = idx % (HH / 4);
            float4 v = *(const float4*)&w[(size_t)n * K2 + k4 * 4];
            ushort4 hh, ll;
            splitw(v.x, hh.x, ll.x); splitw(v.y, hh.y, ll.y);
            splitw(v.z, hh.z, ll.z); splitw(v.w, hh.w, ll.w);
            size_t o = (size_t)n * HH + k4 * 4;
            *(ushort4*)&g_w1h[o] = hh;
            *(ushort4*)&g_w1l[o] = ll;
        }
    }
}

// ---------------------------------------------------------------------------
// Kernel: g_v2[b][n] = vision_mean[b] . W2[n] + bias[n].
// Warp-per-n, 4 batches per warp; vision mean computed inline from partials.
// grid (96, 8), 256 threads. Full fp32 (exact).
// ---------------------------------------------------------------------------
__global__ __launch_bounds__(256) void v2_kernel(const float* __restrict__ w,
                                                 const float* __restrict__ bias) {
    const int lane = threadIdx.x & 31;
    const int wid = threadIdx.x >> 5;
    const int n = blockIdx.x * 8 + wid;         // 0..767
    const int b0 = blockIdx.y * 4;              // 0,4,...,28
    const float invN = 1.0f / (float)NVV;

    const float* wr = w + (size_t)n * K2 + HH;  // W2 row n
    float a0 = 0.f, a1 = 0.f, a2 = 0.f, a3 = 0.f;
    #pragma unroll
    for (int i = 0; i < 6; i++) {
        int k4 = i * 32 + lane;                 // float4 index, coalesced
        float4 wv = *(const float4*)&wr[k4 * 4];
        #pragma unroll
        for (int bb = 0; bb < 4; bb++) {
            const float* pp = &g_vispart[(size_t)((b0 + bb) * 4) * HH + k4 * 4];
            float4 p0 = *(const float4*)(pp);
            float4 p1 = *(const float4*)(pp + HH);
            float4 p2 = *(const float4*)(pp + 2 * HH);
            float4 p3 = *(const float4*)(pp + 3 * HH);
            float sx = (p0.x + p1.x + p2.x + p3.x) * invN;
            float sy = (p0.y + p1.y + p2.y + p3.y) * invN;
            float sz = (p0.z + p1.z + p2.z + p3.z) * invN;
            float sw = (p0.w + p1.w + p2.w + p3.w) * invN;
            float d = sx * wv.x + sy * wv.y + sz * wv.z + sw * wv.w;
            if (bb == 0) a0 += d;
            else if (bb == 1) a1 += d;
            else if (bb == 2) a2 += d;
            else a3 += d;
        }
    }
    #pragma unroll
    for (int off = 16; off; off >>= 1) {
        a0 += __shfl_xor_sync(0xFFFFFFFFu, a0, off);
        a1 += __shfl_xor_sync(0xFFFFFFFFu, a1, off);
        a2 += __shfl_xor_sync(0xFFFFFFFFu, a2, off);
        a3 += __shfl_xor_sync(0xFFFFFFFFu, a3, off);
    }
    if (lane == 0) {
        float bb = bias[n];
        g_v2[(size_t)(b0 + 0) * HH + n] = a0 + bb;
        g_v2[(size_t)(b0 + 1) * HH + n] = a1 + bb;
        g_v2[(size_t)(b0 + 2) * HH + n] = a2 + bb;
        g_v2[(size_t)(b0 + 3) * HH + n] = a3 + bb;
    }
}

// ---------------------------------------------------------------------------
// Kernel: mma.sync fp16 2-term GEMM, single-wave grid, 4-deep pipeline.
// out[m][n] = sum_k A[m][k]*(W1h+W1l)[n][k] + g_v2[m/S][n]
// BM=160, BN=128, BK=32, 24 stages, 4 smem buffers, grid (6,20)=120 CTAs.
// 8 warps 2(m)x4(n); warp tile 80x32.
// ---------------------------------------------------------------------------
#define BM 160
#define NSTG 24
#define NBUF 4
#define ROWH 40                       // padded row length in halfs (80 B)
#define STGA (BM * ROWH)              // A halfs per stage (6400)
#define STGB (128 * ROWH)             // B halfs per stage (5120)
#define GEMM_SMEM ((NBUF * STGA + 2 * NBUF * STGB) * 2)   // 133120 B

__global__ __launch_bounds__(256) void gemm_kernel(float* __restrict__ out) {
    extern __shared__ unsigned short sm[];
    unsigned short* sA  = sm;
    unsigned short* sBh = sA + NBUF * STGA;
    unsigned short* sBl = sBh + NBUF * STGB;

    const int tid = threadIdx.x;
    const int lane = tid & 31;
    const int wid = tid >> 5;
    const int wm = wid >> 2;          // 0..1 -> m offset wm*80
    const int wn = wid & 3;           // 0..3 -> n offset wn*32
    const int n0 = blockIdx.x * 128;
    const int m0 = blockIdx.y * BM;

    const uint32_t bA = smem_u32(sA), bBh = smem_u32(sBh), bBl = smem_u32(sBl);

    float acc[5][4][4];
    #pragma unroll
    for (int i = 0; i < 5; i++)
        #pragma unroll
        for (int j = 0; j < 4; j++)
            #pragma unroll
            for (int r = 0; r < 4; r++) acc[i][j][r] = 0.f;

    auto issue_stage = [&](int s, int buf) {
        const int k0 = s * 32;
        #pragma unroll
        for (int j = 0; j < 3; j++) {
            int idx = tid + j * 256;
            if (idx < BM * 4) {
                int row = idx >> 2;
                int c16 = idx & 3;
                int kk = k0 + c16 * 8;
                uint32_t soff = (uint32_t)(buf * STGA + row * ROWH + c16 * 8) * 2u;
                cpasync16(bA + soff, &g_af[(size_t)(m0 + row) * HH + kk]);
            }
        }
        #pragma unroll
        for (int j = 0; j < 2; j++) {
            int idx = tid + j * 256;
            int row = idx >> 2;
            int c16 = idx & 3;
            int kk = k0 + c16 * 8;
            uint32_t soff = (uint32_t)(buf * STGB + row * ROWH + c16 * 8) * 2u;
            size_t gb = (size_t)(n0 + row) * HH + kk;
            cpasync16(bBh + soff, &g_w1h[gb]);
            cpasync16(bBl + soff, &g_w1l[gb]);
        }
        CP_COMMIT();
    };

    issue_stage(0, 0);
    issue_stage(1, 1);
    issue_stage(2, 2);

    for (int s = 0; s < NSTG; s++) {
        int rem = NSTG - 1 - s;
        if (rem >= 2)      asm volatile("cp.async.wait_group 2;" ::: "memory");
        else if (rem == 1) asm volatile("cp.async.wait_group 1;" ::: "memory");
        else               asm volatile("cp.async.wait_group 0;" ::: "memory");
        __syncthreads();

        if (s + 3 < NSTG) issue_stage(s + 3, (s + 3) % NBUF);

        const int buf = s % NBUF;
        const uint32_t stgA = (uint32_t)(buf * STGA) * 2u;
        const uint32_t stgB = (uint32_t)(buf * STGB) * 2u;

        #pragma unroll
        for (int ks = 0; ks < 2; ks++) {
            const int kh = ks * 16;
            uint32_t a[5][4], b_h[4][2], b_l[4][2];

            #pragma unroll
            for (int ti = 0; ti < 5; ti++) {
                int mr = wm * 80 + ti * 16 + (lane & 15);
                uint32_t off = stgA + (uint32_t)(mr * ROWH + kh + (lane >> 4) * 8) * 2u;
                ldsm_x4(a[ti], bA + off);
            }
            #pragma unroll
            for (int tj = 0; tj < 4; tj++) {
                int nr = wn * 32 + tj * 8 + (lane & 7);
                uint32_t off = stgB + (uint32_t)(nr * ROWH + kh + ((lane >> 3) & 1) * 8) * 2u;
                ldsm_x2(b_h[tj], bBh + off);
                ldsm_x2(b_l[tj], bBl + off);
            }

            #pragma unroll
            for (int ti = 0; ti < 5; ti++)
                #pragma unroll
                for (int tj = 0; tj < 4; tj++) {
                    mma_f16(acc[ti][tj], a[ti], b_h[tj]);
                    mma_f16(acc[ti][tj], a[ti], b_l[tj]);
                }
        }
    }
    __syncthreads();   // all warps done before smem reuse

    // Epilogue: fragments -> padded fp32 smem tile -> coalesced store + v2 add.
    float* st = (float*)sm;                     // 160 x 129 floats = 82560 B
    const int g = lane >> 2;
    const int t2 = (lane & 3) * 2;
    #pragma unroll
    for (int ti = 0; ti < 5; ti++)
        #pragma unroll
        for (int tj = 0; tj < 4; tj++) {
            int r0 = wm * 80 + ti * 16 + g;
            int c0 = wn * 32 + tj * 8 + t2;
            st[r0 * 129 + c0]           = acc[ti][tj][0];
            st[r0 * 129 + c0 + 1]       = acc[ti][tj][1];
            st[(r0 + 8) * 129 + c0]     = acc[ti][tj][2];
            st[(r0 + 8) * 129 + c0 + 1] = acc[ti][tj][3];
        }
    __syncthreads();

    #pragma unroll 4
    for (int it = 0; it < BM * 128 / 256; it++) {
        int q = tid + it * 256;
        int row = q >> 7;
        int col = q & 127;
        int m = m0 + row;
        int b = m / SS;
        out[(size_t)m * HH + n0 + col] = st[row * 129 + col] + g_v2[(size_t)b * HH + n0 + col];
    }
}

// ---------------------------------------------------------------------------
extern "C" void kernel_launch(void* const* d_in, const int* in_sizes, int n_in,
                              void* d_out, int out_size) {
    const float* feat = (const float*)d_in[0];   // (B, NV+T, H) f32
    const int*   mask = (const int*)d_in[1];     // (B, T) i32
    const float* w    = (const float*)d_in[2];   // (H, 2H) f32
    const float* bias = (const float*)d_in[3];   // (H,) f32
    float* out = (float*)d_out;                  // (B, S, H) f32

    mega_kernel<<<NBLK_MEGA, 192>>>(feat, mask, w);
    v2_kernel<<<dim3(96, 8), 256>>>(w, bias);

    cudaFuncSetAttribute(gemm_kernel, cudaFuncAttributeMaxDynamicSharedMemorySize, GEMM_SMEM);
    gemm_kernel<<<dim3(HH / 128, BSROWS / BM), 256, GEMM_SMEM>>>(out);
}

// round 14
// speedup vs baseline: 1.1559x; 1.1559x over previous
#include <cuda_runtime.h>
#include <cuda_fp16.h>
#include <stdint.h>

// Problem constants
#define BB 32
#define TT 2000
#define HH 768
#define SS 100
#define NVV 100
#define BSROWS 3200            // B*S
#define ROWSTRIDE 2100         // NV + T
#define K2 1536                // 2*H

// Block-range layout of mega_kernel (agg blocks handle FOUR segments each)
#define NBLK_AGG  (BSROWS / 4)           // 800
#define NBLK_VIS  (BB * 4)               // 128
#define NBLK_WC   384                    // 384 * 384 f4 = H*H/4
#define NBLK_MEGA (NBLK_AGG + NBLK_VIS + NBLK_WC)   // 1312 (single wave)

// ---------------------------------------------------------------------------
// Scratch (device globals; allocation forbidden)
// ---------------------------------------------------------------------------
__device__ unsigned short g_af[BSROWS * HH];    // fp16 segment means (A)
__device__ unsigned short g_wf[HH * HH];        // fp16 W1 (w[:, :768])
__device__ float g_vispart[BB * 4 * HH];        // partial sums of vision rows
__device__ float g_v2[BB * HH];                 // vision @ W2^T + bias

// ---------------------------------------------------------------------------
// Helpers
// ---------------------------------------------------------------------------
__device__ __forceinline__ uint32_t smem_u32(const void* p) {
    uint32_t a;
    asm("{ .reg .u64 t; cvta.to.shared.u64 t, %1; cvt.u32.u64 %0, t; }" : "=r"(a) : "l"(p));
    return a;
}
__device__ __forceinline__ void cpasync16(uint32_t saddr, const void* g) {
    asm volatile("cp.async.cg.shared.global [%0], [%1], 16;" :: "r"(saddr), "l"(g));
}
#define CP_COMMIT() asm volatile("cp.async.commit_group;" ::: "memory")

__device__ __forceinline__ void ldsm_x4(uint32_t* r, uint32_t addr) {
    asm volatile("ldmatrix.sync.aligned.m8n8.x4.shared.b16 {%0,%1,%2,%3}, [%4];"
                 : "=r"(r[0]), "=r"(r[1]), "=r"(r[2]), "=r"(r[3]) : "r"(addr));
}
__device__ __forceinline__ void ldsm_x2(uint32_t* r, uint32_t addr) {
    asm volatile("ldmatrix.sync.aligned.m8n8.x2.shared.b16 {%0,%1}, [%2];"
                 : "=r"(r[0]), "=r"(r[1]) : "r"(addr));
}
__device__ __forceinline__ void mma_f16(float* c, const uint32_t* a, const uint32_t* b) {
    asm volatile("mma.sync.aligned.m16n8k16.row.col.f32.f16.f16.f32 "
                 "{%0,%1,%2,%3}, {%4,%5,%6,%7}, {%8,%9}, {%0,%1,%2,%3};"
                 : "+f"(c[0]), "+f"(c[1]), "+f"(c[2]), "+f"(c[3])
                 : "r"(a[0]), "r"(a[1]), "r"(a[2]), "r"(a[3]), "r"(b[0]), "r"(b[1]));
}

// pack 4 floats -> 4 fp16 in a uint2
__device__ __forceinline__ uint2 pack4h(float4 v) {
    __half2 p01 = __floats2half2_rn(v.x, v.y);
    __half2 p23 = __floats2half2_rn(v.z, v.w);
    uint2 u;
    u.x = *reinterpret_cast<uint32_t*>(&p01);
    u.y = *reinterpret_cast<uint32_t*>(&p23);
    return u;
}

// accumulate a segment's rows (list in smem) into a float4 and store fp16 mean
__device__ __forceinline__ void seg_accum_store(const float* __restrict__ base,
                                                const unsigned short* __restrict__ list,
                                                int cnt, int h4, size_t orow) {
    float inv = (cnt > 0) ? (1.0f / (float)cnt) : 0.0f;
    float4 acc = make_float4(0.f, 0.f, 0.f, 0.f);
    int i = 0;
    for (; i + 8 <= cnt; i += 8) {
        float4 v[8];
        #pragma unroll
        for (int j = 0; j < 8; j++)
            v[j] = *(const float4*)&base[(size_t)list[i + j] * HH + h4 * 4];
        #pragma unroll
        for (int j = 0; j < 8; j++) {
            acc.x += v[j].x; acc.y += v[j].y; acc.z += v[j].z; acc.w += v[j].w;
        }
    }
    for (; i + 4 <= cnt; i += 4) {
        float4 v[4];
        #pragma unroll
        for (int j = 0; j < 4; j++)
            v[j] = *(const float4*)&base[(size_t)list[i + j] * HH + h4 * 4];
        #pragma unroll
        for (int j = 0; j < 4; j++) {
            acc.x += v[j].x; acc.y += v[j].y; acc.z += v[j].z; acc.w += v[j].w;
        }
    }
    for (; i < cnt; i++) {
        float4 v = *(const float4*)&base[(size_t)list[i] * HH + h4 * 4];
        acc.x += v.x; acc.y += v.y; acc.z += v.z; acc.w += v.w;
    }
    acc.x *= inv; acc.y *= inv; acc.z *= inv; acc.w *= inv;
    *(uint2*)&g_af[orow * HH + h4 * 4] = pack4h(acc);
}

// ---------------------------------------------------------------------------
// Mega kernel: block-range specialization fuses agg (4 segments per block) /
// vision partials / W1 fp16 convert so they overlap on-chip. 192 threads.
// Grid 1312 blocks <= single-wave capacity: everything resident at once.
// ---------------------------------------------------------------------------
__global__ __launch_bounds__(192) void mega_kernel(const float* __restrict__ feat,
                                                   const int* __restrict__ mask,
                                                   const float* __restrict__ w) {
    const int blk = blockIdx.x;

    if (blk < NBLK_AGG) {
        // ---- segment means -> fp16. One block per (b, segment-quad). ----
        int b = blk / (SS / 4);
        int s0 = (blk % (SS / 4)) * 4;          // segments s0..s0+3

        __shared__ unsigned short lists[4][TT];  // 16 KB
        __shared__ int cnts[4];
        if (threadIdx.x < 4) cnts[threadIdx.x] = 0;
        __syncthreads();

        const int* mrow = mask + (size_t)b * TT;
        for (int t = threadIdx.x; t < TT; t += 192) {
            int m = mrow[t] - 1 - s0;           // 0..3 if in this quad
            if ((unsigned)m < 4u) {
                int pos = atomicAdd(&cnts[m], 1);
                lists[m][pos] = (unsigned short)t;
            }
        }
        __syncthreads();

        const float* base = feat + ((size_t)b * ROWSTRIDE + NVV) * HH;
        int h4 = threadIdx.x;                   // 0..191
        size_t row0 = (size_t)b * SS + s0;
        #pragma unroll
        for (int q = 0; q < 4; q++)
            seg_accum_store(base, lists[q], cnts[q], h4, row0 + q);

    } else if (blk < NBLK_AGG + NBLK_VIS) {
        // ---- vision partial sums: 25 rows per block ----
        int idx = blk - NBLK_AGG;
        int b = idx >> 2, part = idx & 3;
        const float* base = feat + ((size_t)b * ROWSTRIDE + part * 25) * HH;
        int h4 = threadIdx.x;
        float4 acc = make_float4(0.f, 0.f, 0.f, 0.f);
        int r = 0;
        for (; r + 4 <= 25; r += 4) {
            float4 v0 = *(const float4*)&base[(size_t)(r + 0) * HH + h4 * 4];
            float4 v1 = *(const float4*)&base[(size_t)(r + 1) * HH + h4 * 4];
            float4 v2 = *(const float4*)&base[(size_t)(r + 2) * HH + h4 * 4];
            float4 v3 = *(const float4*)&base[(size_t)(r + 3) * HH + h4 * 4];
            acc.x += v0.x + v1.x + v2.x + v3.x;
            acc.y += v0.y + v1.y + v2.y + v3.y;
            acc.z += v0.z + v1.z + v2.z + v3.z;
            acc.w += v0.w + v1.w + v2.w + v3.w;
        }
        for (; r < 25; r++) {
            float4 v = *(const float4*)&base[(size_t)r * HH + h4 * 4];
            acc.x += v.x; acc.y += v.y; acc.z += v.z; acc.w += v.w;
        }
        *(float4*)&g_vispart[(size_t)idx * HH + h4 * 4] = acc;

    } else {
        // ---- W1 -> fp16: 384 float4s per block (2 per thread) ----
        int wblk = blk - (NBLK_AGG + NBLK_VIS);
        int i0 = wblk * 384 + threadIdx.x;
        #pragma unroll
        for (int j = 0; j < 2; j++) {
            int idx = i0 + j * 192;
            int n = idx / (HH / 4);
            int k4 = idx % (HH / 4);
            float4 v = *(const float4*)&w[(size_t)n * K2 + k4 * 4];
            *(uint2*)&g_wf[(size_t)n * HH + k4 * 4] = pack4h(v);
        }
    }
}

// ---------------------------------------------------------------------------
// Kernel: g_v2[b][n] = vision_mean[b] . W2[n] + bias[n].
// Warp-per-n, 4 batches per warp; vision mean computed inline from partials.
// grid (96, 8), 256 threads. Full fp32 (exact).
// ---------------------------------------------------------------------------
__global__ __launch_bounds__(256) void v2_kernel(const float* __restrict__ w,
                                                 const float* __restrict__ bias) {
    const int lane = threadIdx.x & 31;
    const int wid = threadIdx.x >> 5;
    const int n = blockIdx.x * 8 + wid;         // 0..767
    const int b0 = blockIdx.y * 4;              // 0,4,...,28
    const float invN = 1.0f / (float)NVV;

    const float* wr = w + (size_t)n * K2 + HH;  // W2 row n
    float a0 = 0.f, a1 = 0.f, a2 = 0.f, a3 = 0.f;
    #pragma unroll
    for (int i = 0; i < 6; i++) {
        int k4 = i * 32 + lane;                 // float4 index, coalesced
        float4 wv = *(const float4*)&wr[k4 * 4];
        #pragma unroll
        for (int bb = 0; bb < 4; bb++) {
            const float* pp = &g_vispart[(size_t)((b0 + bb) * 4) * HH + k4 * 4];
            float4 p0 = *(const float4*)(pp);
            float4 p1 = *(const float4*)(pp + HH);
            float4 p2 = *(const float4*)(pp + 2 * HH);
            float4 p3 = *(const float4*)(pp + 3 * HH);
            float sx = (p0.x + p1.x + p2.x + p3.x) * invN;
            float sy = (p0.y + p1.y + p2.y + p3.y) * invN;
            float sz = (p0.z + p1.z + p2.z + p3.z) * invN;
            float sw = (p0.w + p1.w + p2.w + p3.w) * invN;
            float d = sx * wv.x + sy * wv.y + sz * wv.z + sw * wv.w;
            if (bb == 0) a0 += d;
            else if (bb == 1) a1 += d;
            else if (bb == 2) a2 += d;
            else a3 += d;
        }
    }
    #pragma unroll
    for (int off = 16; off; off >>= 1) {
        a0 += __shfl_xor_sync(0xFFFFFFFFu, a0, off);
        a1 += __shfl_xor_sync(0xFFFFFFFFu, a1, off);
        a2 += __shfl_xor_sync(0xFFFFFFFFu, a2, off);
        a3 += __shfl_xor_sync(0xFFFFFFFFu, a3, off);
    }
    if (lane == 0) {
        float bb = bias[n];
        g_v2[(size_t)(b0 + 0) * HH + n] = a0 + bb;
        g_v2[(size_t)(b0 + 1) * HH + n] = a1 + bb;
        g_v2[(size_t)(b0 + 2) * HH + n] = a2 + bb;
        g_v2[(size_t)(b0 + 3) * HH + n] = a3 + bb;
    }
}

// ---------------------------------------------------------------------------
// Kernel: mma.sync fp16 single-term GEMM, single-wave grid, 4-deep pipeline.
// out[m][n] = sum_k A[m][k]*W1[n][k] + g_v2[m/S][n]   (both fp16, fp32 acc)
// BM=160, BN=128, BK=32, 24 stages, 4 smem buffers, grid (6,20)=120 CTAs.
// 8 warps 2(m)x4(n); warp tile 80x32. 20 MMAs per ks-step (half of 2-term).
// ---------------------------------------------------------------------------
#define BM 160
#define NSTG 24
#define NBUF 4
#define ROWH 40                       // padded row length in halfs (80 B)
#define STGA (BM * ROWH)              // A halfs per stage (6400)
#define STGB (128 * ROWH)             // B halfs per stage (5120)
#define GEMM_SMEM ((NBUF * STGA + NBUF * STGB) * 2)   // 92160 B

__global__ __launch_bounds__(256) void gemm_kernel(float* __restrict__ out) {
    extern __shared__ unsigned short sm[];
    unsigned short* sA = sm;
    unsigned short* sB = sA + NBUF * STGA;

    const int tid = threadIdx.x;
    const int lane = tid & 31;
    const int wid = tid >> 5;
    const int wm = wid >> 2;          // 0..1 -> m offset wm*80
    const int wn = wid & 3;           // 0..3 -> n offset wn*32
    const int n0 = blockIdx.x * 128;
    const int m0 = blockIdx.y * BM;

    const uint32_t bA = smem_u32(sA), bB = smem_u32(sB);

    float acc[5][4][4];
    #pragma unroll
    for (int i = 0; i < 5; i++)
        #pragma unroll
        for (int j = 0; j < 4; j++)
            #pragma unroll
            for (int r = 0; r < 4; r++) acc[i][j][r] = 0.f;

    auto issue_stage = [&](int s, int buf) {
        const int k0 = s * 32;
        #pragma unroll
        for (int j = 0; j < 3; j++) {
            int idx = tid + j * 256;
            if (idx < BM * 4) {
                int row = idx >> 2;
                int c16 = idx & 3;
                int kk = k0 + c16 * 8;
                uint32_t soff = (uint32_t)(buf * STGA + row * ROWH + c16 * 8) * 2u;
                cpasync16(bA + soff, &g_af[(size_t)(m0 + row) * HH + kk]);
            }
        }
        #pragma unroll
        for (int j = 0; j < 2; j++) {
            int idx = tid + j * 256;
            int row = idx >> 2;
            int c16 = idx & 3;
            int kk = k0 + c16 * 8;
            uint32_t soff = (uint32_t)(buf * STGB + row * ROWH + c16 * 8) * 2u;
            cpasync16(bB + soff, &g_wf[(size_t)(n0 + row) * HH + kk]);
        }
        CP_COMMIT();
    };

    issue_stage(0, 0);
    issue_stage(1, 1);
    issue_stage(2, 2);

    for (int s = 0; s < NSTG; s++) {
        int rem = NSTG - 1 - s;
        if (rem >= 2)      asm volatile("cp.async.wait_group 2;" ::: "memory");
        else if (rem == 1) asm volatile("cp.async.wait_group 1;" ::: "memory");
        else               asm volatile("cp.async.wait_group 0;" ::: "memory");
        __syncthreads();

        if (s + 3 < NSTG) issue_stage(s + 3, (s + 3) % NBUF);

        const int buf = s % NBUF;
        const uint32_t stgA = (uint32_t)(buf * STGA) * 2u;
        const uint32_t stgB = (uint32_t)(buf * STGB) * 2u;

        #pragma unroll
        for (int ks = 0; ks < 2; ks++) {
            const int kh = ks * 16;
            uint32_t a[5][4], b[4][2];

            #pragma unroll
            for (int ti = 0; ti < 5; ti++) {
                int mr = wm * 80 + ti * 16 + (lane & 15);
                uint32_t off = stgA + (uint32_t)(mr * ROWH + kh + (lane >> 4) * 8) * 2u;
                ldsm_x4(a[ti], bA + off);
            }
            #pragma unroll
            for (int tj = 0; tj < 4; tj++) {
                int nr = wn * 32 + tj * 8 + (lane & 7);
                uint32_t off = stgB + (uint32_t)(nr * ROWH + kh + ((lane >> 3) & 1) * 8) * 2u;
                ldsm_x2(b[tj], bB + off);
            }

            #pragma unroll
            for (int ti = 0; ti < 5; ti++)
                #pragma unroll
                for (int tj = 0; tj < 4; tj++)
                    mma_f16(acc[ti][tj], a[ti], b[tj]);
        }
    }
    __syncthreads();   // all warps done before smem reuse

    // Epilogue: fragments -> padded fp32 smem tile -> coalesced store + v2 add.
    float* st = (float*)sm;                     // 160 x 129 floats = 82560 B
    const int g = lane >> 2;
    const int t2 = (lane & 3) * 2;
    #pragma unroll
    for (int ti = 0; ti < 5; ti++)
        #pragma unroll
        for (int tj = 0; tj < 4; tj++) {
            int r0 = wm * 80 + ti * 16 + g;
            int c0 = wn * 32 + tj * 8 + t2;
            st[r0 * 129 + c0]           = acc[ti][tj][0];
            st[r0 * 129 + c0 + 1]       = acc[ti][tj][1];
            st[(r0 + 8) * 129 + c0]     = acc[ti][tj][2];
            st[(r0 + 8) * 129 + c0 + 1] = acc[ti][tj][3];
        }
    __syncthreads();

    #pragma unroll 4
    for (int it = 0; it < BM * 128 / 256; it++) {
        int q = tid + it * 256;
        int row = q >> 7;
        int col = q & 127;
        int m = m0 + row;
        int b = m / SS;
        out[(size_t)m * HH + n0 + col] = st[row * 129 + col] + g_v2[(size_t)b * HH + n0 + col];
    }
}

// ---------------------------------------------------------------------------
extern "C" void kernel_launch(void* const* d_in, const int* in_sizes, int n_in,
                              void* d_out, int out_size) {
    const float* feat = (const float*)d_in[0];   // (B, NV+T, H) f32
    const int*   mask = (const int*)d_in[1];     // (B, T) i32
    const float* w    = (const float*)d_in[2];   // (H, 2H) f32
    const float* bias = (const float*)d_in[3];   // (H,) f32
    float* out = (float*)d_out;                  // (B, S, H) f32

    mega_kernel<<<NBLK_MEGA, 192>>>(feat, mask, w);
    v2_kernel<<<dim3(96, 8), 256>>>(w, bias);

    cudaFuncSetAttribute(gemm_kernel, cudaFuncAttributeMaxDynamicSharedMemorySize, GEMM_SMEM);
    gemm_kernel<<<dim3(HH / 128, BSROWS / BM), 256, GEMM_SMEM>>>(out);
}